// round 3
// baseline (speedup 1.0000x reference)
#include <cuda_runtime.h>

#define Nn   100000
#define Ee   3200000
#define NNZn 6400000
#define BN_EPS 1e-5

// ---------------------------------------------------------------------------
// Scratch (device globals; no allocation allowed)
// ---------------------------------------------------------------------------
__device__ __align__(16) float g_z0[Nn * 16];
__device__ __align__(16) float g_z1[Nn * 16];
__device__ __align__(16) float g_acc[Nn * 16];
__device__ double g_stats[32];

__device__ int g_cnt_d[Nn];       // dst histogram
__device__ int g_off_d[Nn + 1];   // CSR offsets for edges by dst
__device__ int g_cur_d[Nn];       // scatter cursors
__device__ int g_esrc[Ee];        // src ids sorted by dst

__device__ int g_cnt_p[Nn];       // pm_rows histogram
__device__ int g_off_p[Nn + 1];
__device__ int g_cur_p[Nn];
__device__ int g_ecol[NNZn];      // cols sorted by row
__device__ float g_eval[NNZn];    // vals sorted by row

// ---------------------------------------------------------------------------
// Helpers
// ---------------------------------------------------------------------------
__device__ __forceinline__ void load16(const float4* __restrict__ p, float f[16]) {
    float4 a = p[0], b = p[1], c = p[2], d = p[3];
    f[0]=a.x; f[1]=a.y; f[2]=a.z; f[3]=a.w;
    f[4]=b.x; f[5]=b.y; f[6]=b.z; f[7]=b.w;
    f[8]=c.x; f[9]=c.y; f[10]=c.z; f[11]=c.w;
    f[12]=d.x; f[13]=d.y; f[14]=d.z; f[15]=d.w;
}
__device__ __forceinline__ void store16(float4* __restrict__ p, const float f[16]) {
    p[0] = make_float4(f[0],  f[1],  f[2],  f[3]);
    p[1] = make_float4(f[4],  f[5],  f[6],  f[7]);
    p[2] = make_float4(f[8],  f[9],  f[10], f[11]);
    p[3] = make_float4(f[12], f[13], f[14], f[15]);
}

// ---------------------------------------------------------------------------
// Histogram: cnt[idx[i]]++ for i in [0, n)
// ---------------------------------------------------------------------------
__global__ void k_hist(const int* __restrict__ idx, int n, int* __restrict__ cnt)
{
    int stride = blockDim.x * gridDim.x;
    for (int i = blockIdx.x * blockDim.x + threadIdx.x; i < n; i += stride)
        atomicAdd(&cnt[idx[i]], 1);
}

// ---------------------------------------------------------------------------
// Exclusive scan of Nn counts (one block per array; blockIdx selects which)
// ---------------------------------------------------------------------------
__global__ void k_scan()
{
    const int* cnt; int* off; int* cur;
    if (blockIdx.x == 0) { cnt = g_cnt_d; off = g_off_d; cur = g_cur_d; }
    else                 { cnt = g_cnt_p; off = g_off_p; cur = g_cur_p; }

    __shared__ int sa[1024], sb[1024];
    int t = threadIdx.x;
    const int chunk = (Nn + 1023) / 1024;
    int beg = t * chunk;
    int end = min(beg + chunk, Nn);

    int s = 0;
    for (int i = beg; i < end; i++) s += cnt[i];
    sa[t] = s;
    __syncthreads();

    // Hillis-Steele inclusive scan over 1024 block sums
    int* in = sa; int* out = sb;
    for (int d = 1; d < 1024; d <<= 1) {
        int v = in[t];
        if (t >= d) v += in[t - d];
        out[t] = v;
        __syncthreads();
        int* tmp = in; in = out; out = tmp;
    }
    int excl = in[t] - s;   // exclusive prefix for this thread's chunk

    int run = excl;
    for (int i = beg; i < end; i++) {
        off[i] = run;
        cur[i] = run;
        run += cnt[i];
    }
    if (end == Nn && beg <= Nn) off[Nn] = run;
}

// ---------------------------------------------------------------------------
// Scatter edges into CSR-by-dst order
// ---------------------------------------------------------------------------
__global__ void k_scatter_edge(const int* __restrict__ src, const int* __restrict__ dst)
{
    int stride = blockDim.x * gridDim.x;
    for (int e = blockIdx.x * blockDim.x + threadIdx.x; e < Ee; e += stride) {
        int p = atomicAdd(&g_cur_d[dst[e]], 1);
        g_esrc[p] = src[e];
    }
}

__global__ void k_scatter_pm(const int* __restrict__ rows, const int* __restrict__ cols,
                             const float* __restrict__ vals)
{
    int stride = blockDim.x * gridDim.x;
    for (int k = blockIdx.x * blockDim.x + threadIdx.x; k < NNZn; k += stride) {
        int p = atomicAdd(&g_cur_p[rows[k]], 1);
        g_ecol[p] = cols[k];
        g_eval[p] = vals[k];
    }
}

// ---------------------------------------------------------------------------
// acc = feat_a @ W_prev + (deg*feat_a) @ W_deg + (sum of all biases)
// ---------------------------------------------------------------------------
__global__ void k_dense(const float4* __restrict__ fa, const float* __restrict__ deg,
                        const float* __restrict__ Wp, const float* __restrict__ bp,
                        const float* __restrict__ Wd, const float* __restrict__ bd,
                        const float* __restrict__ brad, const float* __restrict__ bf)
{
    __shared__ float sWp[256], sWd[256], sb[16];
    int t = threadIdx.x;
    sWp[t] = Wp[t];
    sWd[t] = Wd[t];
    if (t < 16)
        sb[t] = bp[t] + bd[t] + brad[t] + brad[16 + t] + brad[32 + t] + bf[t];
    __syncthreads();

    int i = blockIdx.x * 256 + t;
    if (i >= Nn) return;

    float f[16];
    load16(fa + (size_t)i * 4, f);
    float dg = deg[i];

    float o[16];
#pragma unroll
    for (int j = 0; j < 16; j++) o[j] = sb[j];
#pragma unroll
    for (int r = 0; r < 16; r++) {
        float c = f[r];
        float cd = c * dg;
#pragma unroll
        for (int j = 0; j < 16; j++)
            o[j] += c * sWp[r * 16 + j] + cd * sWd[r * 16 + j];
    }
    store16((float4*)(g_acc + (size_t)i * 16), o);
}

// ---------------------------------------------------------------------------
// Gather hop, warp per node:
//   z[node] = sum over in-edges of zin[src]
// Optional fused projection: acc[node] += z[node] @ W  (W in smem)
// ---------------------------------------------------------------------------
__global__ void k_hop_g(const float4* __restrict__ zin, float4* __restrict__ zout,
                        const float* __restrict__ W)
{
    __shared__ float sW[256];
    if (W) {
        sW[threadIdx.x] = W[threadIdx.x];
        __syncthreads();
    }

    int node = (blockIdx.x * blockDim.x + threadIdx.x) >> 5;
    if (node >= Nn) return;
    int lane = threadIdx.x & 31;
    int sub = lane >> 2;       // 8 edge-subgroups
    int c = lane & 3;          // column quad 4c..4c+3

    int beg = g_off_d[node], end = g_off_d[node + 1];

    float4 s = make_float4(0.f, 0.f, 0.f, 0.f);
    for (int e = beg + sub; e < end; e += 8) {
        float4 v = zin[(size_t)g_esrc[e] * 4 + c];
        s.x += v.x; s.y += v.y; s.z += v.z; s.w += v.w;
    }
#pragma unroll
    for (int m = 4; m <= 16; m <<= 1) {
        s.x += __shfl_xor_sync(0xffffffffu, s.x, m);
        s.y += __shfl_xor_sync(0xffffffffu, s.y, m);
        s.z += __shfl_xor_sync(0xffffffffu, s.z, m);
        s.w += __shfl_xor_sync(0xffffffffu, s.w, m);
    }
    if (zout && sub == 0)
        zout[(size_t)node * 4 + c] = s;

    if (W) {
        // every lane holds z[4c..4c+3]; gather the full 16-vector via width-4 shfl
        float z[16];
#pragma unroll
        for (int q = 0; q < 4; q++) {
            z[q * 4 + 0] = __shfl_sync(0xffffffffu, s.x, q, 4);
            z[q * 4 + 1] = __shfl_sync(0xffffffffu, s.y, q, 4);
            z[q * 4 + 2] = __shfl_sync(0xffffffffu, s.z, q, 4);
            z[q * 4 + 3] = __shfl_sync(0xffffffffu, s.w, q, 4);
        }
        if (sub == 0) {
            float o0 = 0.f, o1 = 0.f, o2 = 0.f, o3 = 0.f;
#pragma unroll
            for (int r = 0; r < 16; r++) {
                float zr = z[r];
                o0 += zr * sW[r * 16 + c * 4 + 0];
                o1 += zr * sW[r * 16 + c * 4 + 1];
                o2 += zr * sW[r * 16 + c * 4 + 2];
                o3 += zr * sW[r * 16 + c * 4 + 3];
            }
            float4* ap = (float4*)(g_acc + (size_t)node * 16) + c;
            float4 a = *ap;
            a.x += o0; a.y += o1; a.z += o2; a.w += o3;
            *ap = a;
        }
    }
}

// ---------------------------------------------------------------------------
// SpMM gather, warp per row: y = sum vals*feat_b[col]; acc[row] += y @ W_fuse
// ---------------------------------------------------------------------------
__global__ void k_spmm_g(const float4* __restrict__ fb, const float* __restrict__ Wf)
{
    __shared__ float sW[256];
    sW[threadIdx.x] = Wf[threadIdx.x];
    __syncthreads();

    int row = (blockIdx.x * blockDim.x + threadIdx.x) >> 5;
    if (row >= Nn) return;
    int lane = threadIdx.x & 31;
    int sub = lane >> 2;
    int c = lane & 3;

    int beg = g_off_p[row], end = g_off_p[row + 1];

    float4 s = make_float4(0.f, 0.f, 0.f, 0.f);
    for (int e = beg + sub; e < end; e += 8) {
        float v = g_eval[e];
        float4 f = fb[(size_t)g_ecol[e] * 4 + c];
        s.x += v * f.x; s.y += v * f.y; s.z += v * f.z; s.w += v * f.w;
    }
#pragma unroll
    for (int m = 4; m <= 16; m <<= 1) {
        s.x += __shfl_xor_sync(0xffffffffu, s.x, m);
        s.y += __shfl_xor_sync(0xffffffffu, s.y, m);
        s.z += __shfl_xor_sync(0xffffffffu, s.z, m);
        s.w += __shfl_xor_sync(0xffffffffu, s.w, m);
    }

    float z[16];
#pragma unroll
    for (int q = 0; q < 4; q++) {
        z[q * 4 + 0] = __shfl_sync(0xffffffffu, s.x, q, 4);
        z[q * 4 + 1] = __shfl_sync(0xffffffffu, s.y, q, 4);
        z[q * 4 + 2] = __shfl_sync(0xffffffffu, s.z, q, 4);
        z[q * 4 + 3] = __shfl_sync(0xffffffffu, s.w, q, 4);
    }
    if (sub == 0) {
        float o0 = 0.f, o1 = 0.f, o2 = 0.f, o3 = 0.f;
#pragma unroll
        for (int r = 0; r < 16; r++) {
            float zr = z[r];
            o0 += zr * sW[r * 16 + c * 4 + 0];
            o1 += zr * sW[r * 16 + c * 4 + 1];
            o2 += zr * sW[r * 16 + c * 4 + 2];
            o3 += zr * sW[r * 16 + c * 4 + 3];
        }
        float4* ap = (float4*)(g_acc + (size_t)row * 16) + c;
        float4 a = *ap;
        a.x += o0; a.y += o1; a.z += o2; a.w += o3;
        *ap = a;
    }
}

// ---------------------------------------------------------------------------
// ReLU on columns 8..15 (in place) + per-column sum / sumsq into g_stats
// ---------------------------------------------------------------------------
__global__ void k_stats()
{
    int lane = threadIdx.x & 31;
    int col = lane & 15;
    bool relu = (col >= 8);

    float sum = 0.f, sq = 0.f;
    int total = Nn * 16;
    int stride = blockDim.x * gridDim.x;
    for (int idx = blockIdx.x * blockDim.x + threadIdx.x; idx < total; idx += stride) {
        float x = g_acc[idx];
        if (relu) {
            x = fmaxf(x, 0.f);
            g_acc[idx] = x;
        }
        sum += x;
        sq += x * x;
    }
    sum += __shfl_xor_sync(0xffffffffu, sum, 16);
    sq  += __shfl_xor_sync(0xffffffffu, sq, 16);
    if (lane < 16) {
        atomicAdd(&g_stats[col],      (double)sum);
        atomicAdd(&g_stats[16 + col], (double)sq);
    }
}

// ---------------------------------------------------------------------------
// BatchNorm finalize
// ---------------------------------------------------------------------------
__global__ void k_final(float4* __restrict__ out,
                        const float* __restrict__ gamma, const float* __restrict__ beta)
{
    __shared__ float s_scale[16], s_shift[16];
    if (threadIdx.x < 16) {
        int c = threadIdx.x;
        double mean = g_stats[c] / (double)Nn;
        double var  = g_stats[16 + c] / (double)Nn - mean * mean;
        float sc = (float)(1.0 / sqrt(var + (double)BN_EPS)) * gamma[c];
        s_scale[c] = sc;
        s_shift[c] = beta[c] - (float)mean * sc;
    }
    __syncthreads();

    int total4 = Nn * 4;
    int stride = blockDim.x * gridDim.x;
    const float4* acc4 = (const float4*)g_acc;
    for (int idx = blockIdx.x * blockDim.x + threadIdx.x; idx < total4; idx += stride) {
        float4 x = acc4[idx];
        int c = (idx & 3) * 4;
        float4 y;
        y.x = x.x * s_scale[c]     + s_shift[c];
        y.y = x.y * s_scale[c + 1] + s_shift[c + 1];
        y.z = x.z * s_scale[c + 2] + s_shift[c + 2];
        y.w = x.w * s_scale[c + 3] + s_shift[c + 3];
        out[idx] = y;
    }
}

// ---------------------------------------------------------------------------
// Launch
// ---------------------------------------------------------------------------
extern "C" void kernel_launch(void* const* d_in, const int* in_sizes, int n_in,
                              void* d_out, int out_size)
{
    const float* feat_a  = (const float*)d_in[0];
    const float* feat_b  = (const float*)d_in[1];
    const float* deg     = (const float*)d_in[2];
    const float* pm_vals = (const float*)d_in[3];
    const float* W_prev  = (const float*)d_in[4];
    const float* b_prev  = (const float*)d_in[5];
    const float* W_deg   = (const float*)d_in[6];
    const float* b_deg   = (const float*)d_in[7];
    const float* W_rad   = (const float*)d_in[8];
    const float* b_rad   = (const float*)d_in[9];
    const float* W_fuse  = (const float*)d_in[10];
    const float* b_fuse  = (const float*)d_in[11];
    const float* gamma   = (const float*)d_in[12];
    const float* beta    = (const float*)d_in[13];
    const int*   src     = (const int*)d_in[14];
    const int*   dst     = (const int*)d_in[15];
    const int*   pm_rows = (const int*)d_in[16];
    const int*   pm_cols = (const int*)d_in[17];
    (void)in_sizes; (void)n_in; (void)out_size;

    void *cntd, *cntp, *statsp, *z0p, *z1p;
    cudaGetSymbolAddress(&cntd, g_cnt_d);
    cudaGetSymbolAddress(&cntp, g_cnt_p);
    cudaGetSymbolAddress(&statsp, g_stats);
    cudaGetSymbolAddress(&z0p, g_z0);
    cudaGetSymbolAddress(&z1p, g_z1);
    float4* z0 = (float4*)z0p;
    float4* z1 = (float4*)z1p;

    const int nb_nodes = (Nn + 255) / 256;
    const int nb_warp  = (Nn * 32 + 255) / 256;   // warp-per-node grids

    cudaMemsetAsync(cntd, 0, Nn * sizeof(int));
    cudaMemsetAsync(cntp, 0, Nn * sizeof(int));
    cudaMemsetAsync(statsp, 0, 32 * sizeof(double));

    // --- CSR builds ---
    k_hist<<<1184, 256>>>(dst, Ee, (int*)cntd);
    k_hist<<<1184, 256>>>(pm_rows, NNZn, (int*)cntp);
    k_scan<<<2, 1024>>>();
    k_scatter_edge<<<1184, 256>>>(src, dst);
    k_scatter_pm<<<1184, 256>>>(pm_rows, pm_cols, pm_vals);

    // --- dense projections (writes acc with all biases folded in) ---
    k_dense<<<nb_nodes, 256>>>((const float4*)feat_a, deg, W_prev, b_prev,
                               W_deg, b_deg, b_rad, b_fuse);

    // --- hops with fused radius projections ---
    k_hop_g<<<nb_warp, 256>>>((const float4*)feat_a, z0, W_rad);        // z1, +W0
    k_hop_g<<<nb_warp, 256>>>((const float4*)z0, z1, W_rad + 256);      // z2, +W1
    k_hop_g<<<nb_warp, 256>>>((const float4*)z1, z0, nullptr);          // t = hop(z2)
    k_hop_g<<<nb_warp, 256>>>((const float4*)z0, nullptr, W_rad + 512); // z4, +W2

    // --- SpMM with fused W_fuse ---
    k_spmm_g<<<nb_warp, 256>>>((const float4*)feat_b, W_fuse);

    // --- ReLU-half + batch stats, then BN finalize ---
    k_stats<<<148 * 8, 256>>>();
    k_final<<<148 * 8, 256>>>((float4*)d_out, gamma, beta);
}

// round 4
// speedup vs baseline: 1.5198x; 1.5198x over previous
#include <cuda_runtime.h>

#define Nn   100000
#define Ee   3200000
#define NNZn 6400000
#define BN_EPS 1e-5

// ---------------------------------------------------------------------------
// Scratch (device globals; no allocation allowed)
// ---------------------------------------------------------------------------
__device__ __align__(16) float g_z0[Nn * 16];
__device__ __align__(16) float g_z1[Nn * 16];
__device__ __align__(16) float g_z2[Nn * 16];
__device__ __align__(16) float g_z3[Nn * 16];
__device__ __align__(16) float g_acc[Nn * 16];
__device__ double g_stats[32];   // [0:16) sums, [16:32) sum of squares

// ---------------------------------------------------------------------------
// Helpers
// ---------------------------------------------------------------------------
__device__ __forceinline__ void red_v4(float* addr, float4 v) {
    asm volatile("red.global.add.v4.f32 [%0], {%1,%2,%3,%4};"
                 :: "l"(addr), "f"(v.x), "f"(v.y), "f"(v.z), "f"(v.w)
                 : "memory");
}

__device__ __forceinline__ void load16(const float4* __restrict__ p, float f[16]) {
    float4 a = p[0], b = p[1], c = p[2], d = p[3];
    f[0]=a.x; f[1]=a.y; f[2]=a.z; f[3]=a.w;
    f[4]=b.x; f[5]=b.y; f[6]=b.z; f[7]=b.w;
    f[8]=c.x; f[9]=c.y; f[10]=c.z; f[11]=c.w;
    f[12]=d.x; f[13]=d.y; f[14]=d.z; f[15]=d.w;
}

__device__ __forceinline__ void store16(float4* __restrict__ p, const float f[16]) {
    p[0] = make_float4(f[0],  f[1],  f[2],  f[3]);
    p[1] = make_float4(f[4],  f[5],  f[6],  f[7]);
    p[2] = make_float4(f[8],  f[9],  f[10], f[11]);
    p[3] = make_float4(f[12], f[13], f[14], f[15]);
}

// ---------------------------------------------------------------------------
// acc = feat_a @ W_prev + (deg*feat_a) @ W_deg + (sum of all biases)
// ---------------------------------------------------------------------------
__global__ void k_dense(const float4* __restrict__ fa, const float* __restrict__ deg,
                        const float* __restrict__ Wp, const float* __restrict__ bp,
                        const float* __restrict__ Wd, const float* __restrict__ bd,
                        const float* __restrict__ brad, const float* __restrict__ bf)
{
    __shared__ float sWp[256], sWd[256], sb[16];
    int t = threadIdx.x;
    sWp[t] = Wp[t];
    sWd[t] = Wd[t];
    if (t < 16)
        sb[t] = bp[t] + bd[t] + brad[t] + brad[16 + t] + brad[32 + t] + bf[t];
    __syncthreads();

    int i = blockIdx.x * 256 + t;
    if (i >= Nn) return;

    float f[16];
    load16(fa + (size_t)i * 4, f);
    float dg = deg[i];

    float o[16];
#pragma unroll
    for (int j = 0; j < 16; j++) o[j] = sb[j];
#pragma unroll
    for (int r = 0; r < 16; r++) {
        float c = f[r];
        float cd = c * dg;
#pragma unroll
        for (int j = 0; j < 16; j++)
            o[j] += c * sWp[r * 16 + j] + cd * sWd[r * 16 + j];
    }
    store16((float4*)(g_acc + (size_t)i * 16), o);
}

// ---------------------------------------------------------------------------
// Hop: zout[dst] += zin[src]  (zout pre-zeroed)
// ---------------------------------------------------------------------------
__global__ void k_hop(const float4* __restrict__ zin, float* __restrict__ zout,
                      const int* __restrict__ src, const int* __restrict__ dst)
{
    int e = blockIdx.x * 256 + threadIdx.x;
    if (e >= Ee) return;
    int s = src[e], d = dst[e];
    const float4* zi = zin + (size_t)s * 4;
    float4 a = zi[0], b = zi[1], c = zi[2], dd = zi[3];
    float* zo = zout + (size_t)d * 16;
    red_v4(zo,      a);
    red_v4(zo + 4,  b);
    red_v4(zo + 8,  c);
    red_v4(zo + 12, dd);
}

// ---------------------------------------------------------------------------
// acc += z @ W   (atomic adds so it can run concurrently with k_spmm)
// ---------------------------------------------------------------------------
__global__ void k_proj(const float4* __restrict__ z, const float* __restrict__ W)
{
    __shared__ float sW[256];
    sW[threadIdx.x] = W[threadIdx.x];
    __syncthreads();

    int i = blockIdx.x * 256 + threadIdx.x;
    if (i >= Nn) return;

    float f[16];
    load16(z + (size_t)i * 4, f);
    float o[16];
#pragma unroll
    for (int j = 0; j < 16; j++) o[j] = 0.f;
#pragma unroll
    for (int r = 0; r < 16; r++) {
        float c = f[r];
#pragma unroll
        for (int j = 0; j < 16; j++)
            o[j] += c * sW[r * 16 + j];
    }
    float* accp = g_acc + (size_t)i * 16;
    red_v4(accp,      make_float4(o[0],  o[1],  o[2],  o[3]));
    red_v4(accp + 4,  make_float4(o[4],  o[5],  o[6],  o[7]));
    red_v4(accp + 8,  make_float4(o[8],  o[9],  o[10], o[11]));
    red_v4(accp + 12, make_float4(o[12], o[13], o[14], o[15]));
}

// ---------------------------------------------------------------------------
// SpMM fused with W_fuse: acc[row] += vals[k] * (feat_b[col] @ W_fuse)
// ---------------------------------------------------------------------------
__global__ void k_spmm(const float4* __restrict__ fb, const float* __restrict__ vals,
                       const int* __restrict__ rows, const int* __restrict__ cols,
                       const float* __restrict__ Wf)
{
    __shared__ float sW[256];
    sW[threadIdx.x] = Wf[threadIdx.x];
    __syncthreads();

    int k = blockIdx.x * 256 + threadIdx.x;
    if (k >= NNZn) return;

    int r = rows[k], c = cols[k];
    float v = vals[k];
    float f[16];
    load16(fb + (size_t)c * 4, f);

    float o[16];
#pragma unroll
    for (int j = 0; j < 16; j++) o[j] = 0.f;
#pragma unroll
    for (int i = 0; i < 16; i++) {
        float fi = f[i] * v;
#pragma unroll
        for (int j = 0; j < 16; j++)
            o[j] += fi * sW[i * 16 + j];
    }
    float* accp = g_acc + (size_t)r * 16;
    red_v4(accp,      make_float4(o[0],  o[1],  o[2],  o[3]));
    red_v4(accp + 4,  make_float4(o[4],  o[5],  o[6],  o[7]));
    red_v4(accp + 8,  make_float4(o[8],  o[9],  o[10], o[11]));
    red_v4(accp + 12, make_float4(o[12], o[13], o[14], o[15]));
}

// ---------------------------------------------------------------------------
// ReLU on columns 8..15 (in place) + per-column sum / sumsq into g_stats
// ---------------------------------------------------------------------------
__global__ void k_stats()
{
    int lane = threadIdx.x & 31;
    int col = lane & 15;
    bool relu = (col >= 8);

    float sum = 0.f, sq = 0.f;
    int total = Nn * 16;
    int stride = blockDim.x * gridDim.x;
    for (int idx = blockIdx.x * blockDim.x + threadIdx.x; idx < total; idx += stride) {
        float x = g_acc[idx];
        if (relu) {
            x = fmaxf(x, 0.f);
            g_acc[idx] = x;
        }
        sum += x;
        sq += x * x;
    }
    sum += __shfl_xor_sync(0xffffffffu, sum, 16);
    sq  += __shfl_xor_sync(0xffffffffu, sq, 16);
    if (lane < 16) {
        atomicAdd(&g_stats[col],      (double)sum);
        atomicAdd(&g_stats[16 + col], (double)sq);
    }
}

// ---------------------------------------------------------------------------
// BatchNorm finalize
// ---------------------------------------------------------------------------
__global__ void k_final(float4* __restrict__ out,
                        const float* __restrict__ gamma, const float* __restrict__ beta)
{
    __shared__ float s_scale[16], s_shift[16];
    if (threadIdx.x < 16) {
        int c = threadIdx.x;
        double mean = g_stats[c] / (double)Nn;
        double var  = g_stats[16 + c] / (double)Nn - mean * mean;
        float sc = (float)(1.0 / sqrt(var + (double)BN_EPS)) * gamma[c];
        s_scale[c] = sc;
        s_shift[c] = beta[c] - (float)mean * sc;
    }
    __syncthreads();

    int total4 = Nn * 4;
    int stride = blockDim.x * gridDim.x;
    const float4* acc4 = (const float4*)g_acc;
    for (int idx = blockIdx.x * blockDim.x + threadIdx.x; idx < total4; idx += stride) {
        float4 x = acc4[idx];
        int c = (idx & 3) * 4;
        float4 y;
        y.x = x.x * s_scale[c]     + s_shift[c];
        y.y = x.y * s_scale[c + 1] + s_shift[c + 1];
        y.z = x.z * s_scale[c + 2] + s_shift[c + 2];
        y.w = x.w * s_scale[c + 3] + s_shift[c + 3];
        out[idx] = y;
    }
}

// ---------------------------------------------------------------------------
// Launch: hop chain on the main stream; SpMM forked onto a side stream so the
// graph executes it concurrently (hops are L2-bound, SpMM is DRAM-bound).
// ---------------------------------------------------------------------------
extern "C" void kernel_launch(void* const* d_in, const int* in_sizes, int n_in,
                              void* d_out, int out_size)
{
    const float* feat_a  = (const float*)d_in[0];
    const float* feat_b  = (const float*)d_in[1];
    const float* deg     = (const float*)d_in[2];
    const float* pm_vals = (const float*)d_in[3];
    const float* W_prev  = (const float*)d_in[4];
    const float* b_prev  = (const float*)d_in[5];
    const float* W_deg   = (const float*)d_in[6];
    const float* b_deg   = (const float*)d_in[7];
    const float* W_rad   = (const float*)d_in[8];
    const float* b_rad   = (const float*)d_in[9];
    const float* W_fuse  = (const float*)d_in[10];
    const float* b_fuse  = (const float*)d_in[11];
    const float* gamma   = (const float*)d_in[12];
    const float* beta    = (const float*)d_in[13];
    const int*   src     = (const int*)d_in[14];
    const int*   dst     = (const int*)d_in[15];
    const int*   pm_rows = (const int*)d_in[16];
    const int*   pm_cols = (const int*)d_in[17];
    (void)in_sizes; (void)n_in; (void)out_size;

    // Side stream + events (host resources, created once; no device memory)
    static cudaStream_t s2 = nullptr;
    static cudaEvent_t ev_fork = nullptr, ev_join = nullptr;
    if (!s2) {
        cudaStreamCreateWithFlags(&s2, cudaStreamNonBlocking);
        cudaEventCreateWithFlags(&ev_fork, cudaEventDisableTiming);
        cudaEventCreateWithFlags(&ev_join, cudaEventDisableTiming);
    }

    void *z0p, *z1p, *z2p, *z3p, *statsp;
    cudaGetSymbolAddress(&z0p, g_z0);
    cudaGetSymbolAddress(&z1p, g_z1);
    cudaGetSymbolAddress(&z2p, g_z2);
    cudaGetSymbolAddress(&z3p, g_z3);
    cudaGetSymbolAddress(&statsp, g_stats);
    float* z0 = (float*)z0p;
    float* z1 = (float*)z1p;
    float* z2 = (float*)z2p;
    float* z3 = (float*)z3p;

    const int nb_nodes = (Nn + 255) / 256;
    const int nb_edges = (Ee + 255) / 256;
    const int nb_nnz   = (NNZn + 255) / 256;
    const size_t zbytes = (size_t)Nn * 16 * sizeof(float);

    // upfront zeroing
    cudaMemsetAsync(z0p, 0, zbytes);
    cudaMemsetAsync(z1p, 0, zbytes);
    cudaMemsetAsync(z2p, 0, zbytes);
    cudaMemsetAsync(z3p, 0, zbytes);
    cudaMemsetAsync(statsp, 0, 32 * sizeof(double));

    // dense projections (plain writes of acc incl. all biases)
    k_dense<<<nb_nodes, 256>>>((const float4*)feat_a, deg, W_prev, b_prev,
                               W_deg, b_deg, b_rad, b_fuse);

    // ---- fork: SpMM runs concurrently with the hop chain ----
    cudaEventRecord(ev_fork, 0);
    cudaStreamWaitEvent(s2, ev_fork, 0);
    k_spmm<<<nb_nnz, 256, 0, s2>>>((const float4*)feat_b, pm_vals,
                                   pm_rows, pm_cols, W_fuse);
    cudaEventRecord(ev_join, s2);

    // ---- hop chain (serial, L2-bound) ----
    k_hop<<<nb_edges, 256>>>((const float4*)feat_a, z0, src, dst);
    k_proj<<<nb_nodes, 256>>>((const float4*)z0, W_rad);

    k_hop<<<nb_edges, 256>>>((const float4*)z0, z1, src, dst);
    k_proj<<<nb_nodes, 256>>>((const float4*)z1, W_rad + 256);

    k_hop<<<nb_edges, 256>>>((const float4*)z1, z2, src, dst);
    k_hop<<<nb_edges, 256>>>((const float4*)z2, z3, src, dst);
    k_proj<<<nb_nodes, 256>>>((const float4*)z3, W_rad + 512);

    // ---- join, then epilogue ----
    cudaStreamWaitEvent(0, ev_join, 0);
    k_stats<<<148 * 8, 256>>>();
    k_final<<<148 * 8, 256>>>((float4*)d_out, gamma, beta);
}